// round 16
// baseline (speedup 1.0000x reference)
#include <cuda_runtime.h>
#include <cuda_bf16.h>
#include <cstdint>

#define NN   50000
#define EE   800000
#define ETOT (EE + NN)
#define SCANB 196

// ---------------- scratch ----------------
__device__ float g_xw  [NN * 256];
__device__ float g_xw1 [NN * 128];
__device__ float g_al  [NN * 8];
__device__ float g_al1 [NN * 2];
__device__ __nv_bfloat16 g_xhi [NN * 256], g_xlo [NN * 256];
__device__ __nv_bfloat16 g_hhi [NN * 256], g_hlo [NN * 256];
__device__ __nv_bfloat16 g_h1hi[NN * 256], g_h1lo[NN * 256];
__device__ __nv_bfloat16 g_h2hi[NN * 128], g_h2lo[NN * 128];
__device__ __nv_bfloat16 g_WpThi[256 * 256], g_WpTlo[256 * 256];
__device__ __nv_bfloat16 g_W0Thi[256 * 256], g_W0Tlo[256 * 256];
__device__ __nv_bfloat16 g_W1Thi[128 * 256], g_W1Tlo[128 * 256];
__device__ __nv_bfloat16 g_WoThi[128 * 128], g_WoTlo[128 * 128];
__device__ int   g_count[NN];
__device__ int   g_cursor[NN];
__device__ int   g_rowstart[NN + 1];
__device__ int   g_bsum[SCANB];
__device__ int   g_esrc[ETOT];
__device__ int   g_bad = 0;   // monotone across replays: 0 -> int64 mode, 1 -> int32

__device__ __forceinline__ void f2hilo(float x, __nv_bfloat16& h, __nv_bfloat16& l) {
    h = __float2bfloat16(x);
    l = __float2bfloat16(x - __bfloat162float(h));
}

__device__ __forceinline__ void cpa16(uint32_t d, const void* s, int srcsz) {
    asm volatile("cp.async.cg.shared.global [%0], [%1], 16, %2;"
                 :: "r"(d), "l"(s), "r"(srcsz));
}
#define CP_COMMIT() asm volatile("cp.async.commit_group;" ::: "memory")
#define CP_WAIT0()  asm volatile("cp.async.wait_group 0;" ::: "memory")
#define CP_WAIT1()  asm volatile("cp.async.wait_group 1;" ::: "memory")

__device__ __forceinline__ void ldsm_x4(uint32_t addr, uint32_t& r0, uint32_t& r1,
                                        uint32_t& r2, uint32_t& r3) {
    asm volatile("ldmatrix.sync.aligned.m8n8.x4.shared.b16 {%0,%1,%2,%3}, [%4];"
                 : "=r"(r0), "=r"(r1), "=r"(r2), "=r"(r3) : "r"(addr));
}
__device__ __forceinline__ void mma16816(float* d, const uint32_t* a, const uint32_t* b) {
    asm volatile("mma.sync.aligned.m16n8k16.row.col.f32.bf16.bf16.f32 "
                 "{%0,%1,%2,%3}, {%4,%5,%6,%7}, {%8,%9}, {%0,%1,%2,%3};"
                 : "+f"(d[0]), "+f"(d[1]), "+f"(d[2]), "+f"(d[3])
                 : "r"(a[0]), "r"(a[1]), "r"(a[2]), "r"(a[3]), "r"(b[0]), "r"(b[1]));
}

__device__ __forceinline__ int edge_at(const void* ei, int pos, int m64) {
    return m64 ? (int)((const long long*)ei)[pos] : ((const int*)ei)[pos];
}

// =====================  prep: init + detect + cvtA + cvtW in ONE launch  =====================
__device__ __forceinline__ void cvtw1(const float* W, __nv_bfloat16* hi, __nv_bfloat16* lo,
                                      int K, int Nd, int i) {
    int k = i / Nd, n = i % Nd;
    __nv_bfloat16 h, l;
    f2hilo(W[i], h, l);
    hi[n * K + k] = h;
    lo[n * K + k] = l;
}
#define PREP_INIT   200      // zero count/cursor
#define PREP_DET    400      // detect dtype
#define PREP_CVA    12500    // x -> hi/lo (float4 granularity)
#define PREP_CVW    704      // 180224 weight elements / 256
#define PREP_TOTAL  (PREP_INIT + PREP_DET + PREP_CVA + PREP_CVW)
__global__ void k_prep(const float* __restrict__ x, const void* __restrict__ ei,
                       const float* __restrict__ Wp, const float* __restrict__ W0,
                       const float* __restrict__ W1, const float* __restrict__ Wo) {
    int b = blockIdx.x, t = threadIdx.x;
    if (b < PREP_INIT) {
        int i = b * 256 + t;
        if (i < NN) { g_count[i] = 0; g_cursor[i] = 0; }
        if (b == 0 && t == 0) g_rowstart[NN] = ETOT;
    } else if (b < PREP_INIT + PREP_DET) {
        int stride = PREP_DET * 256;
        for (int e = (b - PREP_INIT) * 256 + t; e < EE; e += stride) {
            long long v = ((const long long*)ei)[e];
            if (v < 0 || v >= NN) { g_bad = 1; return; }
        }
    } else if (b < PREP_INIT + PREP_DET + PREP_CVA) {
        int i = (b - PREP_INIT - PREP_DET) * 256 + t;
        float4 v = ((const float4*)x)[i];
        __nv_bfloat16 h0, h1, h2, h3, l0, l1, l2, l3;
        f2hilo(v.x, h0, l0); f2hilo(v.y, h1, l1); f2hilo(v.z, h2, l2); f2hilo(v.w, h3, l3);
        ((__nv_bfloat162*)g_xhi)[i * 2]     = __nv_bfloat162(h0, h1);
        ((__nv_bfloat162*)g_xhi)[i * 2 + 1] = __nv_bfloat162(h2, h3);
        ((__nv_bfloat162*)g_xlo)[i * 2]     = __nv_bfloat162(l0, l1);
        ((__nv_bfloat162*)g_xlo)[i * 2 + 1] = __nv_bfloat162(l2, l3);
    } else {
        int i = (b - PREP_INIT - PREP_DET - PREP_CVA) * 256 + t;
        if (i < 65536)        cvtw1(Wp, g_WpThi, g_WpTlo, 256, 256, i);
        else if (i < 131072)  cvtw1(W0, g_W0Thi, g_W0Tlo, 256, 256, i - 65536);
        else if (i < 163840)  cvtw1(W1, g_W1Thi, g_W1Tlo, 256, 128, i - 131072);
        else if (i < 180224)  cvtw1(Wo, g_WoThi, g_WoTlo, 128, 128, i - 163840);
    }
}

// =====================  scan  =====================
__global__ void k_scan1() {
    __shared__ int wsum[8];
    int b = blockIdx.x, t = threadIdx.x;
    int idx = b * 256 + t;
    int lane = t & 31, wid = t >> 5;
    int v = (idx < NN) ? g_count[idx] : 0;
    int x = v;
#pragma unroll
    for (int off = 1; off < 32; off <<= 1) {
        int y = __shfl_up_sync(0xffffffffu, x, off);
        if (lane >= off) x += y;
    }
    if (lane == 31) wsum[wid] = x;
    __syncthreads();
    if (wid == 0) {
        int w = (lane < 8) ? wsum[lane] : 0;
#pragma unroll
        for (int off = 1; off < 8; off <<= 1) {
            int y = __shfl_up_sync(0xffffffffu, w, off);
            if (lane >= off) w += y;
        }
        if (lane < 8) wsum[lane] = w;
    }
    __syncthreads();
    int base = (wid > 0) ? wsum[wid - 1] : 0;
    if (idx < NN) g_rowstart[idx] = base + x - v;
    if (t == 255) g_bsum[b] = base + x;
}
__global__ void k_scan2() {
    __shared__ int red[8];
    __shared__ int boff;
    int b = blockIdx.x, t = threadIdx.x;
    int lane = t & 31, wid = t >> 5;
    int s = 0;
    for (int i = t; i < b; i += 256) s += g_bsum[i];
#pragma unroll
    for (int off = 16; off; off >>= 1) s += __shfl_xor_sync(0xffffffffu, s, off);
    if (lane == 0) red[wid] = s;
    __syncthreads();
    if (t == 0) {
        int tot = 0;
#pragma unroll
        for (int i = 0; i < 8; i++) tot += red[i];
        boff = tot;
    }
    __syncthreads();
    int idx = b * 256 + t;
    if (idx < NN) g_rowstart[idx] += boff;
}

// =====================  ldmatrix + mma.sync bf16 split GEMM (+fused edge work)  =====================
// OMODE: 0 fp32 C, 1 bf16 hi/lo. EDGE: 0 none, 1 count-prefix, 2 scatter-prefix.
#define LDC 132

template<bool RELU, bool BIAS, int OMODE, bool NORM, int ALH, int TM, int EDGE>
__global__ __launch_bounds__(256, 2)
void k_gemm_mma(const __nv_bfloat16* __restrict__ Ahi, const __nv_bfloat16* __restrict__ Alo,
                const __nv_bfloat16* __restrict__ Bhi, const __nv_bfloat16* __restrict__ Blo,
                const float* __restrict__ bias, float* __restrict__ C,
                __nv_bfloat16* __restrict__ Chi, __nv_bfloat16* __restrict__ Clo,
                const float* __restrict__ aS, const float* __restrict__ aD,
                const void* __restrict__ eip, int nEdgeBlk,
                int M, int K, int Nd) {
    constexpr int NJ   = (TM == 128) ? 4 : 2;
    constexpr int TPR  = 256 / TM;
    constexpr int CPT  = 128 / TPR;
    constexpr int A_B  = TM * 80;
    constexpr int B_AHI = 0, B_ALO = A_B, B_BHI = 2 * A_B, B_BLO = 2 * A_B + 10240;
    constexpr int BUFB = 2 * A_B + 20480;

    // ---- fused edge-work prefix blocks (return before touching SMEM) ----
    if (EDGE) {
        int bid = blockIdx.x;
        if (bid < nEdgeBlk) {
            int e = bid * 256 + threadIdx.x;
            if (e < ETOT) {
                int m64 = (g_bad == 0);
                if (EDGE == 1) {
                    int d = (e < EE) ? edge_at(eip, EE + e, m64) : (e - EE);
                    atomicAdd(&g_count[d], 1);
                } else {
                    int s, d;
                    if (e < EE) { s = edge_at(eip, e, m64); d = edge_at(eip, EE + e, m64); }
                    else        { s = d = e - EE; }
                    int slot = g_rowstart[d] + atomicAdd(&g_cursor[d], 1);
                    g_esrc[slot] = s;
                }
            }
            return;
        }
    }
    const int gb  = blockIdx.x - (EDGE ? nEdgeBlk : 0);
    const int gBX = (M + TM - 1) / TM;
    const int bm  = (gb % gBX) * TM;
    const int bn  = (gb / gBX) * 128;

    extern __shared__ char smem[];
    const uint32_t sb0 = (uint32_t)__cvta_generic_to_shared(smem);
    float* sC  = (float*)smem;
    float* sSS = (float*)(smem + TM * LDC * 4);

    const int tid = threadIdx.x;
    const int wid = tid >> 5;
    const int lane = tid & 31;
    const int wm = (TM == 128) ? (wid & 3) : (wid & 1);
    const int wn = (TM == 128) ? (wid >> 2) : (wid >> 1);
    const int NC = K >> 5;

    uint32_t offA[2];
#pragma unroll
    for (int i = 0; i < 2; i++)
        offA[i] = (uint32_t)((wm * 32 + i * 16 + (lane & 15)) * 80 + (lane >> 4) * 16);
    uint32_t offB[NJ];
#pragma unroll
    for (int j = 0; j < NJ; j++)
        offB[j] = (uint32_t)((wn * 16 * NJ + j * 16 + (lane >> 4) * 8 + (lane & 7)) * 80 +
                             ((lane >> 3) & 1) * 16);

    float acc[2][2 * NJ][4];
#pragma unroll
    for (int i = 0; i < 2; i++)
#pragma unroll
        for (int j = 0; j < 2 * NJ; j++)
#pragma unroll
            for (int e = 0; e < 4; e++)
                acc[i][j][e] = 0.f;

    auto load_chunk = [&](int buf, int kc) {
        uint32_t sb = sb0 + buf * BUFB;
#pragma unroll
        for (int i = tid; i < 512; i += 256) {
            int r = i >> 2, seg = i & 3;
            uint32_t off = (uint32_t)(r * 80 + seg * 16);
            size_t gbb = (size_t)(bn + r) * K + kc * 32 + seg * 8;
            cpa16(sb + B_BHI + off, Bhi + gbb, 16);
            cpa16(sb + B_BLO + off, Blo + gbb, 16);
            if (r < TM) {
                int arow = bm + r;
                int sz = (arow < M) ? 16 : 0;
                if (arow >= M) arow = M - 1;
                size_t ga = (size_t)arow * K + kc * 32 + seg * 8;
                cpa16(sb + B_AHI + off, Ahi + ga, sz);
                cpa16(sb + B_ALO + off, Alo + ga, sz);
            }
        }
    };

    load_chunk(0, 0);
    CP_COMMIT();

    for (int kc = 0; kc < NC; kc++) {
        if (kc + 1 < NC) {
            load_chunk((kc + 1) & 1, kc + 1);
            CP_COMMIT();
            CP_WAIT1();
        } else {
            CP_WAIT0();
        }
        __syncthreads();

        const uint32_t bufb = sb0 + (kc & 1) * BUFB;
#pragma unroll
        for (int ks = 0; ks < 2; ks++) {
            const uint32_t ko = (uint32_t)(ks * 32);
            uint32_t ah[2][4], al[2][4], bb[NJ][4];
#pragma unroll
            for (int i = 0; i < 2; i++) {
                ldsm_x4(bufb + B_AHI + offA[i] + ko, ah[i][0], ah[i][1], ah[i][2], ah[i][3]);
                ldsm_x4(bufb + B_ALO + offA[i] + ko, al[i][0], al[i][1], al[i][2], al[i][3]);
            }
#pragma unroll
            for (int j = 0; j < NJ; j++)
                ldsm_x4(bufb + B_BHI + offB[j] + ko, bb[j][0], bb[j][1], bb[j][2], bb[j][3]);
#pragma unroll
            for (int j = 0; j < NJ; j++)
#pragma unroll
                for (int i = 0; i < 2; i++) {
                    mma16816(acc[i][2 * j],     ah[i], &bb[j][0]);
                    mma16816(acc[i][2 * j + 1], ah[i], &bb[j][2]);
                }
#pragma unroll
            for (int j = 0; j < NJ; j++)
#pragma unroll
                for (int i = 0; i < 2; i++) {
                    mma16816(acc[i][2 * j],     al[i], &bb[j][0]);
                    mma16816(acc[i][2 * j + 1], al[i], &bb[j][2]);
                }
#pragma unroll
            for (int j = 0; j < NJ; j++)
                ldsm_x4(bufb + B_BLO + offB[j] + ko, bb[j][0], bb[j][1], bb[j][2], bb[j][3]);
#pragma unroll
            for (int j = 0; j < NJ; j++)
#pragma unroll
                for (int i = 0; i < 2; i++) {
                    mma16816(acc[i][2 * j],     ah[i], &bb[j][0]);
                    mma16816(acc[i][2 * j + 1], ah[i], &bb[j][2]);
                }
        }
        __syncthreads();
    }

    // accumulators -> SMEM C
    {
        int qr = lane >> 2, qc = (lane & 3) << 1;
#pragma unroll
        for (int i = 0; i < 2; i++)
#pragma unroll
            for (int nc = 0; nc < 2 * NJ; nc++) {
                float* p = &sC[(wm * 32 + i * 16 + qr) * LDC + wn * 16 * NJ + nc * 8 + qc];
                *(float2*)p = make_float2(acc[i][nc][0], acc[i][nc][1]);
                *(float2*)(p + 8 * LDC) = make_float2(acc[i][nc][2], acc[i][nc][3]);
            }
    }
    __syncthreads();

    // fused epilogue
    {
        int r = tid / TPR, c0 = (tid % TPR) * CPT;
        int row = bm + r;
        if (NORM) {
            if ((tid % TPR) == 0) sSS[r] = 0.f;
            __syncthreads();
            float ss = 0.f;
            if (row < M) {
#pragma unroll
                for (int j = 0; j < CPT; j += 4) {
                    float4 v = *(float4*)&sC[r * LDC + c0 + j];
                    int col = bn + c0 + j;
                    v.x += bias[col + 0]; v.y += bias[col + 1];
                    v.z += bias[col + 2]; v.w += bias[col + 3];
                    ss += v.x * v.x + v.y * v.y + v.z * v.z + v.w * v.w;
                }
            }
            atomicAdd(&sSS[r], ss);
            __syncthreads();
            if (row < M) {
                float sc = 1.f / fmaxf(sqrtf(sSS[r]), 1e-12f);
#pragma unroll
                for (int j = 0; j < CPT; j += 4) {
                    float4 v = *(float4*)&sC[r * LDC + c0 + j];
                    int col = bn + c0 + j;
                    v.x = (v.x + bias[col + 0]) * sc;
                    v.y = (v.y + bias[col + 1]) * sc;
                    v.z = (v.z + bias[col + 2]) * sc;
                    v.w = (v.w + bias[col + 3]) * sc;
                    *(float4*)&C[(size_t)row * Nd + col] = v;
                }
            }
        } else if (row < M) {
            float ps = 0.f, pd = 0.f;
#pragma unroll
            for (int j = 0; j < CPT; j += 4) {
                float4 v = *(float4*)&sC[r * LDC + c0 + j];
                int col = bn + c0 + j;
                if (BIAS) {
                    v.x += bias[col + 0]; v.y += bias[col + 1];
                    v.z += bias[col + 2]; v.w += bias[col + 3];
                }
                if (RELU) {
                    v.x = fmaxf(v.x, 0.f); v.y = fmaxf(v.y, 0.f);
                    v.z = fmaxf(v.z, 0.f); v.w = fmaxf(v.w, 0.f);
                }
                if (ALH) {
                    float4 a = *(const float4*)(aS + col);
                    float4 b = *(const float4*)(aD + col);
                    ps += v.x * a.x + v.y * a.y + v.z * a.z + v.w * a.w;
                    pd += v.x * b.x + v.y * b.y + v.z * b.z + v.w * b.w;
                }
                size_t o = (size_t)row * Nd + col;
                if (OMODE == 0) {
                    *(float4*)&C[o] = v;
                } else {
                    __nv_bfloat16 h0, h1, h2, h3, l0, l1, l2, l3;
                    f2hilo(v.x, h0, l0); f2hilo(v.y, h1, l1);
                    f2hilo(v.z, h2, l2); f2hilo(v.w, h3, l3);
                    *(__nv_bfloat162*)(Chi + o)     = __nv_bfloat162(h0, h1);
                    *(__nv_bfloat162*)(Chi + o + 2) = __nv_bfloat162(h2, h3);
                    *(__nv_bfloat162*)(Clo + o)     = __nv_bfloat162(l0, l1);
                    *(__nv_bfloat162*)(Clo + o + 2) = __nv_bfloat162(l2, l3);
                }
            }
            if (ALH == 4) {
                int head = (bn + c0) >> 6;
                g_al[(size_t)row * 8 + head]     = ps;
                g_al[(size_t)row * 8 + 4 + head] = pd;
            } else if (ALH == 1) {
#pragma unroll
                for (int off = TPR >> 1; off; off >>= 1) {
                    ps += __shfl_xor_sync(0xffffffffu, ps, off);
                    pd += __shfl_xor_sync(0xffffffffu, pd, off);
                }
                if ((tid % TPR) == 0) {
                    g_al1[(size_t)row * 2]     = ps;
                    g_al1[(size_t)row * 2 + 1] = pd;
                }
            }
        }
    }
}
#define SMEM_G128 (2 * (2 * 128 * 80 + 20480))   // 81920
#define SMEM_G64  (2 * (2 * 64 * 80 + 20480))    // 61440

// ============  aggregation layer 0 (unchanged hot loop)  ============
__global__ void k_agg0(const float* __restrict__ b0, const float* __restrict__ g0,
                       const float* __restrict__ be0) {
    int d = (blockIdx.x * blockDim.x + threadIdx.x) >> 5;
    int lane = threadIdx.x & 31;
    if (d >= NN) return;
    int beg = g_rowstart[d], end = g_rowstart[d + 1];
    float ald_l = g_al[d * 8 + 4 + (lane & 3)];
    int h0i = lane >> 4;
    float4 acc0 = {0, 0, 0, 0}, acc1 = {0, 0, 0, 0};
    float den0 = 0.f, den1 = 0.f;
    for (int i = beg; i < end; i += 8) {
        int ii = i + (lane >> 2);
        bool valid = ii < end;
        int s_i = g_esrc[valid ? ii : beg];
        float e = g_al[s_i * 8 + (lane & 3)] + ald_l;
        e = (e > 0.f) ? e : 0.2f * e;
        float w_i = valid ? __expf(e) : 0.f;
#pragma unroll
        for (int k = 0; k < 8; k++) {
            float w0 = __shfl_sync(0xffffffffu, w_i, k * 4 + h0i);
            float w1 = __shfl_sync(0xffffffffu, w_i, k * 4 + 2 + h0i);
            int   s  = __shfl_sync(0xffffffffu, s_i, k * 4);
            const float4* xr = (const float4*)&g_xw[(size_t)s * 256];
            float4 v0 = xr[lane], v1 = xr[32 + lane];
            acc0.x += w0 * v0.x; acc0.y += w0 * v0.y; acc0.z += w0 * v0.z; acc0.w += w0 * v0.w;
            acc1.x += w1 * v1.x; acc1.y += w1 * v1.y; acc1.z += w1 * v1.z; acc1.w += w1 * v1.w;
            den0 += w0; den1 += w1;
        }
    }
    float r0 = 1.f / den0, r1 = 1.f / den1;
    int ch0 = lane * 4, ch1 = 128 + lane * 4;
    float4 bb0 = *(const float4*)(b0 + ch0), bb1 = *(const float4*)(b0 + ch1);
    float t0[4] = {acc0.x * r0 + bb0.x, acc0.y * r0 + bb0.y, acc0.z * r0 + bb0.z, acc0.w * r0 + bb0.w};
    float t1[4] = {acc1.x * r1 + bb1.x, acc1.y * r1 + bb1.y, acc1.z * r1 + bb1.z, acc1.w * r1 + bb1.w};
    float s1 = 0.f, s2 = 0.f;
#pragma unroll
    for (int k = 0; k < 4; k++) { s1 += t0[k] + t1[k]; s2 += t0[k] * t0[k] + t1[k] * t1[k]; }
#pragma unroll
    for (int off = 16; off; off >>= 1) {
        s1 += __shfl_xor_sync(0xffffffffu, s1, off);
        s2 += __shfl_xor_sync(0xffffffffu, s2, off);
    }
    float mu = s1 * (1.f / 256.f);
    float var = s2 * (1.f / 256.f) - mu * mu;
    float rs = rsqrtf(var + 1e-5f);
    float4 gg0 = *(const float4*)(g0 + ch0),  gg1 = *(const float4*)(g0 + ch1);
    float4 ee0 = *(const float4*)(be0 + ch0), ee1 = *(const float4*)(be0 + ch1);
    size_t o0 = (size_t)d * 256 + ch0, o1 = (size_t)d * 256 + ch1;
    float fh0[8], fl0[8];
    {
        uint2 a = *(const uint2*)(g_hhi + o0), b = *(const uint2*)(g_hlo + o0);
        uint2 c = *(const uint2*)(g_hhi + o1), e = *(const uint2*)(g_hlo + o1);
        float2 p;
        p = __bfloat1622float2(*(__nv_bfloat162*)&a.x); fh0[0] = p.x; fh0[1] = p.y;
        p = __bfloat1622float2(*(__nv_bfloat162*)&a.y); fh0[2] = p.x; fh0[3] = p.y;
        p = __bfloat1622float2(*(__nv_bfloat162*)&b.x); fl0[0] = p.x; fl0[1] = p.y;
        p = __bfloat1622float2(*(__nv_bfloat162*)&b.y); fl0[2] = p.x; fl0[3] = p.y;
        p = __bfloat1622float2(*(__nv_bfloat162*)&c.x); fh0[4] = p.x; fh0[5] = p.y;
        p = __bfloat1622float2(*(__nv_bfloat162*)&c.y); fh0[6] = p.x; fh0[7] = p.y;
        p = __bfloat1622float2(*(__nv_bfloat162*)&e.x); fl0[4] = p.x; fl0[5] = p.y;
        p = __bfloat1622float2(*(__nv_bfloat162*)&e.y); fl0[6] = p.x; fl0[7] = p.y;
    }
    float gg0a[4] = {gg0.x, gg0.y, gg0.z, gg0.w};
    float ee0a[4] = {ee0.x, ee0.y, ee0.z, ee0.w};
    float gg1a[4] = {gg1.x, gg1.y, gg1.z, gg1.w};
    float ee1a[4] = {ee1.x, ee1.y, ee1.z, ee1.w};
    float y0[4], y1[4];
#pragma unroll
    for (int k = 0; k < 4; k++) {
        y0[k] = fmaxf((t0[k] - mu) * rs * gg0a[k] + ee0a[k] + (fh0[k] + fl0[k]), 0.f);
        y1[k] = fmaxf((t1[k] - mu) * rs * gg1a[k] + ee1a[k] + (fh0[4 + k] + fl0[4 + k]), 0.f);
    }
    __nv_bfloat16 h[8], l[8];
#pragma unroll
    for (int k = 0; k < 4; k++) { f2hilo(y0[k], h[k], l[k]); f2hilo(y1[k], h[4 + k], l[4 + k]); }
    *(__nv_bfloat162*)(g_h1hi + o0)     = __nv_bfloat162(h[0], h[1]);
    *(__nv_bfloat162*)(g_h1hi + o0 + 2) = __nv_bfloat162(h[2], h[3]);
    *(__nv_bfloat162*)(g_h1hi + o1)     = __nv_bfloat162(h[4], h[5]);
    *(__nv_bfloat162*)(g_h1hi + o1 + 2) = __nv_bfloat162(h[6], h[7]);
    *(__nv_bfloat162*)(g_h1lo + o0)     = __nv_bfloat162(l[0], l[1]);
    *(__nv_bfloat162*)(g_h1lo + o0 + 2) = __nv_bfloat162(l[2], l[3]);
    *(__nv_bfloat162*)(g_h1lo + o1)     = __nv_bfloat162(l[4], l[5]);
    *(__nv_bfloat162*)(g_h1lo + o1 + 2) = __nv_bfloat162(l[6], l[7]);
}

// ============  aggregation layer 1 (unchanged hot loop)  ============
__global__ void k_agg1(const float* __restrict__ b1, const float* __restrict__ g1,
                       const float* __restrict__ be1) {
    int d = (blockIdx.x * blockDim.x + threadIdx.x) >> 5;
    int lane = threadIdx.x & 31;
    if (d >= NN) return;
    int beg = g_rowstart[d], end = g_rowstart[d + 1];
    float ald = g_al1[d * 2 + 1];
    float4 acc = {0, 0, 0, 0};
    float den = 0.f;
    for (int i = beg; i < end; i += 8) {
        int ii = i + (lane & 7);
        bool valid = ii < end;
        int s_i = g_esrc[valid ? ii : beg];
        float e = g_al1[s_i * 2] + ald;
        e = (e > 0.f) ? e : 0.2f * e;
        float w_i = valid ? __expf(e) : 0.f;
#pragma unroll
        for (int k = 0; k < 8; k++) {
            float w = __shfl_sync(0xffffffffu, w_i, k);
            int   s = __shfl_sync(0xffffffffu, s_i, k);
            float4 v = *(const float4*)&g_xw1[(size_t)s * 128 + lane * 4];
            acc.x += w * v.x; acc.y += w * v.y; acc.z += w * v.z; acc.w += w * v.w;
            den += w;
        }
    }
    float r = 1.f / den;
    int ch = lane * 4;
    float4 bb = *(const float4*)(b1 + ch);
    float t[4] = {acc.x * r + bb.x, acc.y * r + bb.y, acc.z * r + bb.z, acc.w * r + bb.w};
    float s1 = 0.f, s2 = 0.f;
#pragma unroll
    for (int k = 0; k < 4; k++) { s1 += t[k]; s2 += t[k] * t[k]; }
#pragma unroll
    for (int off = 16; off; off >>= 1) {
        s1 += __shfl_xor_sync(0xffffffffu, s1, off);
        s2 += __shfl_xor_sync(0xffffffffu, s2, off);
    }
    float mu = s1 * (1.f / 128.f);
    float var = s2 * (1.f / 128.f) - mu * mu;
    float rs = rsqrtf(var + 1e-5f);
    float4 gg = *(const float4*)(g1 + ch);
    float4 ee = *(const float4*)(be1 + ch);
    float y[4] = {
        (t[0] - mu) * rs * gg.x + ee.x, (t[1] - mu) * rs * gg.y + ee.y,
        (t[2] - mu) * rs * gg.z + ee.z, (t[3] - mu) * rs * gg.w + ee.w};
    __nv_bfloat16 h[4], l[4];
#pragma unroll
    for (int k = 0; k < 4; k++) f2hilo(y[k], h[k], l[k]);
    size_t o = (size_t)d * 128 + ch;
    *(__nv_bfloat162*)(g_h2hi + o)     = __nv_bfloat162(h[0], h[1]);
    *(__nv_bfloat162*)(g_h2hi + o + 2) = __nv_bfloat162(h[2], h[3]);
    *(__nv_bfloat162*)(g_h2lo + o)     = __nv_bfloat162(l[0], l[1]);
    *(__nv_bfloat162*)(g_h2lo + o + 2) = __nv_bfloat162(l[2], l[3]);
}

// =====================  launch  =====================
extern "C" void kernel_launch(void* const* d_in, const int* in_sizes, int n_in,
                              void* d_out, int out_size) {
    const float* x   = (const float*)d_in[0];
    const void*  ei  = d_in[1];
    const float* Wp  = (const float*)d_in[2];
    const float* bp  = (const float*)d_in[3];
    const float* W0  = (const float*)d_in[4];
    const float* as0 = (const float*)d_in[5];
    const float* ad0 = (const float*)d_in[6];
    const float* b0  = (const float*)d_in[7];
    const float* W1  = (const float*)d_in[8];
    const float* as1 = (const float*)d_in[9];
    const float* ad1 = (const float*)d_in[10];
    const float* b1  = (const float*)d_in[11];
    const float* g0  = (const float*)d_in[12];
    const float* be0 = (const float*)d_in[13];
    const float* g1  = (const float*)d_in[14];
    const float* be1 = (const float*)d_in[15];
    const float* Wo  = (const float*)d_in[16];
    const float* bo  = (const float*)d_in[17];
    float* out = (float*)d_out;

    void *p_xw, *p_xw1;
    void *p_xhi, *p_xlo, *p_hhi, *p_hlo, *p_h1hi, *p_h1lo, *p_h2hi, *p_h2lo;
    void *p_WpThi, *p_WpTlo, *p_W0Thi, *p_W0Tlo, *p_W1Thi, *p_W1Tlo, *p_WoThi, *p_WoTlo;
    cudaGetSymbolAddress(&p_xw,   g_xw);
    cudaGetSymbolAddress(&p_xw1,  g_xw1);
    cudaGetSymbolAddress(&p_xhi,  g_xhi);   cudaGetSymbolAddress(&p_xlo,  g_xlo);
    cudaGetSymbolAddress(&p_hhi,  g_hhi);   cudaGetSymbolAddress(&p_hlo,  g_hlo);
    cudaGetSymbolAddress(&p_h1hi, g_h1hi);  cudaGetSymbolAddress(&p_h1lo, g_h1lo);
    cudaGetSymbolAddress(&p_h2hi, g_h2hi);  cudaGetSymbolAddress(&p_h2lo, g_h2lo);
    cudaGetSymbolAddress(&p_WpThi, g_WpThi); cudaGetSymbolAddress(&p_WpTlo, g_WpTlo);
    cudaGetSymbolAddress(&p_W0Thi, g_W0Thi); cudaGetSymbolAddress(&p_W0Tlo, g_W0Tlo);
    cudaGetSymbolAddress(&p_W1Thi, g_W1Thi); cudaGetSymbolAddress(&p_W1Tlo, g_W1Tlo);
    cudaGetSymbolAddress(&p_WoThi, g_WoThi); cudaGetSymbolAddress(&p_WoTlo, g_WoTlo);

    const int nodeBlocks = (NN + 7) / 8;
    const int edgeBlocks = (ETOT + 255) / 256;
    const int gB128 = (NN + 127) / 128;
    const int gB64  = (NN + 63) / 64;

    cudaFuncSetAttribute((const void*)k_gemm_mma<true,  true,  1, false, 0, 128, 1>,
                         cudaFuncAttributeMaxDynamicSharedMemorySize, SMEM_G128);
    cudaFuncSetAttribute((const void*)k_gemm_mma<false, false, 0, false, 4, 128, 2>,
                         cudaFuncAttributeMaxDynamicSharedMemorySize, SMEM_G128);
    cudaFuncSetAttribute((const void*)k_gemm_mma<false, false, 0, false, 1, 64, 0>,
                         cudaFuncAttributeMaxDynamicSharedMemorySize, SMEM_G64);
    cudaFuncSetAttribute((const void*)k_gemm_mma<false, true,  0, true,  0, 64, 0>,
                         cudaFuncAttributeMaxDynamicSharedMemorySize, SMEM_G64);

    // 1: prep (init + detect + cvtA + cvtW)
    k_prep<<<PREP_TOTAL, 256>>>(x, ei, Wp, W0, W1, Wo);

    // 2: count (prefix blocks) + GEMM1: h = relu(x@Wp + bp) -> bf16 hi/lo
    k_gemm_mma<true, true, 1, false, 0, 128, 1>
        <<<edgeBlocks + gB128 * 2, 256, SMEM_G128>>>(
        (const __nv_bfloat16*)p_xhi, (const __nv_bfloat16*)p_xlo,
        (const __nv_bfloat16*)p_WpThi, (const __nv_bfloat16*)p_WpTlo,
        bp, nullptr, (__nv_bfloat16*)p_hhi, (__nv_bfloat16*)p_hlo,
        nullptr, nullptr, ei, edgeBlocks, NN, 256, 256);

    // 3-4: scan
    k_scan1<<<SCANB, 256>>>();
    k_scan2<<<SCANB, 256>>>();

    // 5: scatter (prefix blocks) + GEMM2: xw = h@W0, logits al0 fused
    k_gemm_mma<false, false, 0, false, 4, 128, 2>
        <<<edgeBlocks + gB128 * 2, 256, SMEM_G128>>>(
        (const __nv_bfloat16*)p_hhi, (const __nv_bfloat16*)p_hlo,
        (const __nv_bfloat16*)p_W0Thi, (const __nv_bfloat16*)p_W0Tlo,
        nullptr, (float*)p_xw, nullptr, nullptr, as0, ad0, ei, edgeBlocks, NN, 256, 256);

    // 6: agg0 + LN0 + residual + relu -> h1 hi/lo
    k_agg0<<<nodeBlocks, 256>>>(b0, g0, be0);

    // 7: GEMM3 (TM=64): xw1 = h1@W1, logits al1 fused
    k_gemm_mma<false, false, 0, false, 1, 64, 0><<<gB64, 256, SMEM_G64>>>(
        (const __nv_bfloat16*)p_h1hi, (const __nv_bfloat16*)p_h1lo,
        (const __nv_bfloat16*)p_W1Thi, (const __nv_bfloat16*)p_W1Tlo,
        nullptr, (float*)p_xw1, nullptr, nullptr, as1, ad1, nullptr, 0, NN, 256, 128);

    // 8: agg1 + LN1 -> h2 hi/lo
    k_agg1<<<nodeBlocks, 256>>>(b1, g1, be1);

    // 9: GEMM4 (TM=64): out = rownorm(h2@Wo + bo)
    k_gemm_mma<false, true, 0, true, 0, 64, 0><<<gB64, 256, SMEM_G64>>>(
        (const __nv_bfloat16*)p_h2hi, (const __nv_bfloat16*)p_h2lo,
        (const __nv_bfloat16*)p_WoThi, (const __nv_bfloat16*)p_WoTlo,
        bo, out, nullptr, nullptr, nullptr, nullptr, nullptr, 0, NN, 128, 128);
}

// round 17
// speedup vs baseline: 1.0140x; 1.0140x over previous
#include <cuda_runtime.h>
#include <cuda_bf16.h>
#include <cuda_fp16.h>
#include <cstdint>

#define NN   50000
#define EE   800000
#define ETOT (EE + NN)
#define SCANB 196

// ---------------- scratch ----------------
__device__ __half g_xwh [NN * 256];   // h@W0 features, fp16 (agg0)
__device__ __half g_xw1h[NN * 128];   // h1@W1 features, fp16 (agg1)
__device__ float g_al  [NN * 8];
__device__ float g_al1 [NN * 2];
__device__ __nv_bfloat16 g_xhi [NN * 256], g_xlo [NN * 256];
__device__ __nv_bfloat16 g_hhi [NN * 256], g_hlo [NN * 256];
__device__ __nv_bfloat16 g_h1hi[NN * 256], g_h1lo[NN * 256];
__device__ __nv_bfloat16 g_h2hi[NN * 128], g_h2lo[NN * 128];
__device__ __nv_bfloat16 g_WpThi[256 * 256], g_WpTlo[256 * 256];
__device__ __nv_bfloat16 g_W0Thi[256 * 256], g_W0Tlo[256 * 256];
__device__ __nv_bfloat16 g_W1Thi[128 * 256], g_W1Tlo[128 * 256];
__device__ __nv_bfloat16 g_WoThi[128 * 128], g_WoTlo[128 * 128];
__device__ int   g_count[NN];
__device__ int   g_cursor[NN];
__device__ int   g_rowstart[NN + 1];
__device__ int   g_bsum[SCANB];
__device__ int   g_esrc[ETOT];
__device__ int   g_bad = 0;

__device__ __forceinline__ void f2hilo(float x, __nv_bfloat16& h, __nv_bfloat16& l) {
    h = __float2bfloat16(x);
    l = __float2bfloat16(x - __bfloat162float(h));
}

__device__ __forceinline__ void cpa16(uint32_t d, const void* s, int srcsz) {
    asm volatile("cp.async.cg.shared.global [%0], [%1], 16, %2;"
                 :: "r"(d), "l"(s), "r"(srcsz));
}
#define CP_COMMIT() asm volatile("cp.async.commit_group;" ::: "memory")
#define CP_WAIT0()  asm volatile("cp.async.wait_group 0;" ::: "memory")
#define CP_WAIT1()  asm volatile("cp.async.wait_group 1;" ::: "memory")

__device__ __forceinline__ void ldsm_x4(uint32_t addr, uint32_t& r0, uint32_t& r1,
                                        uint32_t& r2, uint32_t& r3) {
    asm volatile("ldmatrix.sync.aligned.m8n8.x4.shared.b16 {%0,%1,%2,%3}, [%4];"
                 : "=r"(r0), "=r"(r1), "=r"(r2), "=r"(r3) : "r"(addr));
}
__device__ __forceinline__ void mma16816(float* d, const uint32_t* a, const uint32_t* b) {
    asm volatile("mma.sync.aligned.m16n8k16.row.col.f32.bf16.bf16.f32 "
                 "{%0,%1,%2,%3}, {%4,%5,%6,%7}, {%8,%9}, {%0,%1,%2,%3};"
                 : "+f"(d[0]), "+f"(d[1]), "+f"(d[2]), "+f"(d[3])
                 : "r"(a[0]), "r"(a[1]), "r"(a[2]), "r"(a[3]), "r"(b[0]), "r"(b[1]));
}

__device__ __forceinline__ int edge_at(const void* ei, int pos, int m64) {
    return m64 ? (int)((const long long*)ei)[pos] : ((const int*)ei)[pos];
}

// =====================  prep: init + detect + cvtA + cvtW  =====================
__device__ __forceinline__ void cvtw1(const float* W, __nv_bfloat16* hi, __nv_bfloat16* lo,
                                      int K, int Nd, int i) {
    int k = i / Nd, n = i % Nd;
    __nv_bfloat16 h, l;
    f2hilo(W[i], h, l);
    hi[n * K + k] = h;
    lo[n * K + k] = l;
}
#define PREP_INIT   200
#define PREP_DET    400
#define PREP_CVA    12500
#define PREP_CVW    704
#define PREP_TOTAL  (PREP_INIT + PREP_DET + PREP_CVA + PREP_CVW)
__global__ void k_prep(const float* __restrict__ x, const void* __restrict__ ei,
                       const float* __restrict__ Wp, const float* __restrict__ W0,
                       const float* __restrict__ W1, const float* __restrict__ Wo) {
    int b = blockIdx.x, t = threadIdx.x;
    if (b < PREP_INIT) {
        int i = b * 256 + t;
        if (i < NN) { g_count[i] = 0; g_cursor[i] = 0; }
        if (b == 0 && t == 0) g_rowstart[NN] = ETOT;
    } else if (b < PREP_INIT + PREP_DET) {
        int stride = PREP_DET * 256;
        for (int e = (b - PREP_INIT) * 256 + t; e < EE; e += stride) {
            long long v = ((const long long*)ei)[e];
            if (v < 0 || v >= NN) { g_bad = 1; return; }
        }
    } else if (b < PREP_INIT + PREP_DET + PREP_CVA) {
        int i = (b - PREP_INIT - PREP_DET) * 256 + t;
        float4 v = ((const float4*)x)[i];
        __nv_bfloat16 h0, h1, h2, h3, l0, l1, l2, l3;
        f2hilo(v.x, h0, l0); f2hilo(v.y, h1, l1); f2hilo(v.z, h2, l2); f2hilo(v.w, h3, l3);
        ((__nv_bfloat162*)g_xhi)[i * 2]     = __nv_bfloat162(h0, h1);
        ((__nv_bfloat162*)g_xhi)[i * 2 + 1] = __nv_bfloat162(h2, h3);
        ((__nv_bfloat162*)g_xlo)[i * 2]     = __nv_bfloat162(l0, l1);
        ((__nv_bfloat162*)g_xlo)[i * 2 + 1] = __nv_bfloat162(l2, l3);
    } else {
        int i = (b - PREP_INIT - PREP_DET - PREP_CVA) * 256 + t;
        if (i < 65536)        cvtw1(Wp, g_WpThi, g_WpTlo, 256, 256, i);
        else if (i < 131072)  cvtw1(W0, g_W0Thi, g_W0Tlo, 256, 256, i - 65536);
        else if (i < 163840)  cvtw1(W1, g_W1Thi, g_W1Tlo, 256, 128, i - 131072);
        else if (i < 180224)  cvtw1(Wo, g_WoThi, g_WoTlo, 128, 128, i - 163840);
    }
}

// =====================  scan  =====================
__global__ void k_scan1() {
    __shared__ int wsum[8];
    int b = blockIdx.x, t = threadIdx.x;
    int idx = b * 256 + t;
    int lane = t & 31, wid = t >> 5;
    int v = (idx < NN) ? g_count[idx] : 0;
    int x = v;
#pragma unroll
    for (int off = 1; off < 32; off <<= 1) {
        int y = __shfl_up_sync(0xffffffffu, x, off);
        if (lane >= off) x += y;
    }
    if (lane == 31) wsum[wid] = x;
    __syncthreads();
    if (wid == 0) {
        int w = (lane < 8) ? wsum[lane] : 0;
#pragma unroll
        for (int off = 1; off < 8; off <<= 1) {
            int y = __shfl_up_sync(0xffffffffu, w, off);
            if (lane >= off) w += y;
        }
        if (lane < 8) wsum[lane] = w;
    }
    __syncthreads();
    int base = (wid > 0) ? wsum[wid - 1] : 0;
    if (idx < NN) g_rowstart[idx] = base + x - v;
    if (t == 255) g_bsum[b] = base + x;
}
__global__ void k_scan2() {
    __shared__ int red[8];
    __shared__ int boff;
    int b = blockIdx.x, t = threadIdx.x;
    int lane = t & 31, wid = t >> 5;
    int s = 0;
    for (int i = t; i < b; i += 256) s += g_bsum[i];
#pragma unroll
    for (int off = 16; off; off >>= 1) s += __shfl_xor_sync(0xffffffffu, s, off);
    if (lane == 0) red[wid] = s;
    __syncthreads();
    if (t == 0) {
        int tot = 0;
#pragma unroll
        for (int i = 0; i < 8; i++) tot += red[i];
        boff = tot;
    }
    __syncthreads();
    int idx = b * 256 + t;
    if (idx < NN) g_rowstart[idx] += boff;
}

// =====================  GEMM (+fused edge prefix)  =====================
// OMODE: 0 fp32 C, 1 bf16 hi/lo, 2 fp16 single. EDGE: 0 none, 1 count, 2 scatter.
#define LDC 132

template<bool RELU, bool BIAS, int OMODE, bool NORM, int ALH, int TM, int EDGE>
__global__ __launch_bounds__(256, 2)
void k_gemm_mma(const __nv_bfloat16* __restrict__ Ahi, const __nv_bfloat16* __restrict__ Alo,
                const __nv_bfloat16* __restrict__ Bhi, const __nv_bfloat16* __restrict__ Blo,
                const float* __restrict__ bias, float* __restrict__ C,
                __nv_bfloat16* __restrict__ Chi, __nv_bfloat16* __restrict__ Clo,
                const float* __restrict__ aS, const float* __restrict__ aD,
                const void* __restrict__ eip, int nEdgeBlk,
                int M, int K, int Nd) {
    constexpr int NJ   = (TM == 128) ? 4 : 2;
    constexpr int TPR  = 256 / TM;
    constexpr int CPT  = 128 / TPR;
    constexpr int A_B  = TM * 80;
    constexpr int B_AHI = 0, B_ALO = A_B, B_BHI = 2 * A_B, B_BLO = 2 * A_B + 10240;
    constexpr int BUFB = 2 * A_B + 20480;

    if (EDGE) {
        int bid = blockIdx.x;
        if (bid < nEdgeBlk) {
            int e = bid * 256 + threadIdx.x;
            if (e < ETOT) {
                int m64 = (g_bad == 0);
                if (EDGE == 1) {
                    int d = (e < EE) ? edge_at(eip, EE + e, m64) : (e - EE);
                    atomicAdd(&g_count[d], 1);
                } else {
                    int s, d;
                    if (e < EE) { s = edge_at(eip, e, m64); d = edge_at(eip, EE + e, m64); }
                    else        { s = d = e - EE; }
                    int slot = g_rowstart[d] + atomicAdd(&g_cursor[d], 1);
                    g_esrc[slot] = s;
                }
            }
            return;
        }
    }
    const int gb  = blockIdx.x - (EDGE ? nEdgeBlk : 0);
    const int gBX = (M + TM - 1) / TM;
    const int bm  = (gb % gBX) * TM;
    const int bn  = (gb / gBX) * 128;

    extern __shared__ char smem[];
    const uint32_t sb0 = (uint32_t)__cvta_generic_to_shared(smem);
    float* sC  = (float*)smem;
    float* sSS = (float*)(smem + TM * LDC * 4);

    const int tid = threadIdx.x;
    const int wid = tid >> 5;
    const int lane = tid & 31;
    const int wm = (TM == 128) ? (wid & 3) : (wid & 1);
    const int wn = (TM == 128) ? (wid >> 2) : (wid >> 1);
    const int NC = K >> 5;

    uint32_t offA[2];
#pragma unroll
    for (int i = 0; i < 2; i++)
        offA[i] = (uint32_t)((wm * 32 + i * 16 + (lane & 15)) * 80 + (lane >> 4) * 16);
    uint32_t offB[NJ];
#pragma unroll
    for (int j = 0; j < NJ; j++)
        offB[j] = (uint32_t)((wn * 16 * NJ + j * 16 + (lane >> 4) * 8 + (lane & 7)) * 80 +
                             ((lane >> 3) & 1) * 16);

    float acc[2][2 * NJ][4];
#pragma unroll
    for (int i = 0; i < 2; i++)
#pragma unroll
        for (int j = 0; j < 2 * NJ; j++)
#pragma unroll
            for (int e = 0; e < 4; e++)
                acc[i][j][e] = 0.f;

    auto load_chunk = [&](int buf, int kc) {
        uint32_t sb = sb0 + buf * BUFB;
#pragma unroll
        for (int i = tid; i < 512; i += 256) {
            int r = i >> 2, seg = i & 3;
            uint32_t off = (uint32_t)(r * 80 + seg * 16);
            size_t gbb = (size_t)(bn + r) * K + kc * 32 + seg * 8;
            cpa16(sb + B_BHI + off, Bhi + gbb, 16);
            cpa16(sb + B_BLO + off, Blo + gbb, 16);
            if (r < TM) {
                int arow = bm + r;
                int sz = (arow < M) ? 16 : 0;
                if (arow >= M) arow = M - 1;
                size_t ga = (size_t)arow * K + kc * 32 + seg * 8;
                cpa16(sb + B_AHI + off, Ahi + ga, sz);
                cpa16(sb + B_ALO + off, Alo + ga, sz);
            }
        }
    };

    load_chunk(0, 0);
    CP_COMMIT();

    for (int kc = 0; kc < NC; kc++) {
        if (kc + 1 < NC) {
            load_chunk((kc + 1) & 1, kc + 1);
            CP_COMMIT();
            CP_WAIT1();
        } else {
            CP_WAIT0();
        }
        __syncthreads();

        const uint32_t bufb = sb0 + (kc & 1) * BUFB;
#pragma unroll
        for (int ks = 0; ks < 2; ks++) {
            const uint32_t ko = (uint32_t)(ks * 32);
            uint32_t ah[2][4], al[2][4], bb[NJ][4];
#pragma unroll
            for (int i = 0; i < 2; i++) {
                ldsm_x4(bufb + B_AHI + offA[i] + ko, ah[i][0], ah[i][1], ah[i][2], ah[i][3]);
                ldsm_x4(bufb + B_ALO + offA[i] + ko, al[i][0], al[i][1], al[i][2], al[i][3]);
            }
#pragma unroll
            for (int j = 0; j < NJ; j++)
                ldsm_x4(bufb + B_BHI + offB[j] + ko, bb[j][0], bb[j][1], bb[j][2], bb[j][3]);
#pragma unroll
            for (int j = 0; j < NJ; j++)
#pragma unroll
                for (int i = 0; i < 2; i++) {
                    mma16816(acc[i][2 * j],     ah[i], &bb[j][0]);
                    mma16816(acc[i][2 * j + 1], ah[i], &bb[j][2]);
                }
#pragma unroll
            for (int j = 0; j < NJ; j++)
#pragma unroll
                for (int i = 0; i < 2; i++) {
                    mma16816(acc[i][2 * j],     al[i], &bb[j][0]);
                    mma16816(acc[i][2 * j + 1], al[i], &bb[j][2]);
                }
#pragma unroll
            for (int j = 0; j < NJ; j++)
                ldsm_x4(bufb + B_BLO + offB[j] + ko, bb[j][0], bb[j][1], bb[j][2], bb[j][3]);
#pragma unroll
            for (int j = 0; j < NJ; j++)
#pragma unroll
                for (int i = 0; i < 2; i++) {
                    mma16816(acc[i][2 * j],     ah[i], &bb[j][0]);
                    mma16816(acc[i][2 * j + 1], ah[i], &bb[j][2]);
                }
        }
        __syncthreads();
    }

    {
        int qr = lane >> 2, qc = (lane & 3) << 1;
#pragma unroll
        for (int i = 0; i < 2; i++)
#pragma unroll
            for (int nc = 0; nc < 2 * NJ; nc++) {
                float* p = &sC[(wm * 32 + i * 16 + qr) * LDC + wn * 16 * NJ + nc * 8 + qc];
                *(float2*)p = make_float2(acc[i][nc][0], acc[i][nc][1]);
                *(float2*)(p + 8 * LDC) = make_float2(acc[i][nc][2], acc[i][nc][3]);
            }
    }
    __syncthreads();

    // fused epilogue
    {
        int r = tid / TPR, c0 = (tid % TPR) * CPT;
        int row = bm + r;
        if (NORM) {
            if ((tid % TPR) == 0) sSS[r] = 0.f;
            __syncthreads();
            float ss = 0.f;
            if (row < M) {
#pragma unroll
                for (int j = 0; j < CPT; j += 4) {
                    float4 v = *(float4*)&sC[r * LDC + c0 + j];
                    int col = bn + c0 + j;
                    v.x += bias[col + 0]; v.y += bias[col + 1];
                    v.z += bias[col + 2]; v.w += bias[col + 3];
                    ss += v.x * v.x + v.y * v.y + v.z * v.z + v.w * v.w;
                }
            }
            atomicAdd(&sSS[r], ss);
            __syncthreads();
            if (row < M) {
                float sc = 1.f / fmaxf(sqrtf(sSS[r]), 1e-12f);
#pragma unroll
                for (int j = 0; j < CPT; j += 4) {
                    float4 v = *(float4*)&sC[r * LDC + c0 + j];
                    int col = bn + c0 + j;
                    v.x = (v.x + bias[col + 0]) * sc;
                    v.y = (v.y + bias[col + 1]) * sc;
                    v.z = (v.z + bias[col + 2]) * sc;
                    v.w = (v.w + bias[col + 3]) * sc;
                    *(float4*)&C[(size_t)row * Nd + col] = v;
                }
            }
        } else if (row < M) {
            float ps = 0.f, pd = 0.f;
#pragma unroll
            for (int j = 0; j < CPT; j += 4) {
                float4 v = *(float4*)&sC[r * LDC + c0 + j];
                int col = bn + c0 + j;
                if (BIAS) {
                    v.x += bias[col + 0]; v.y += bias[col + 1];
                    v.z += bias[col + 2]; v.w += bias[col + 3];
                }
                if (RELU) {
                    v.x = fmaxf(v.x, 0.f); v.y = fmaxf(v.y, 0.f);
                    v.z = fmaxf(v.z, 0.f); v.w = fmaxf(v.w, 0.f);
                }
                if (ALH) {
                    float4 a = *(const float4*)(aS + col);
                    float4 b = *(const float4*)(aD + col);
                    ps += v.x * a.x + v.y * a.y + v.z * a.z + v.w * a.w;
                    pd += v.x * b.x + v.y * b.y + v.z * b.z + v.w * b.w;
                }
                size_t o = (size_t)row * Nd + col;
                if (OMODE == 0) {
                    *(float4*)&C[o] = v;
                } else if (OMODE == 1) {
                    __nv_bfloat16 h0, h1, h2, h3, l0, l1, l2, l3;
                    f2hilo(v.x, h0, l0); f2hilo(v.y, h1, l1);
                    f2hilo(v.z, h2, l2); f2hilo(v.w, h3, l3);
                    *(__nv_bfloat162*)(Chi + o)     = __nv_bfloat162(h0, h1);
                    *(__nv_bfloat162*)(Chi + o + 2) = __nv_bfloat162(h2, h3);
                    *(__nv_bfloat162*)(Clo + o)     = __nv_bfloat162(l0, l1);
                    *(__nv_bfloat162*)(Clo + o + 2) = __nv_bfloat162(l2, l3);
                } else {  // OMODE == 2: fp16 single
                    __half* Hp = (__half*)Chi;
                    *(__half2*)(Hp + o)     = __floats2half2_rn(v.x, v.y);
                    *(__half2*)(Hp + o + 2) = __floats2half2_rn(v.z, v.w);
                }
            }
            if (ALH == 4) {
                int head = (bn + c0) >> 6;
                g_al[(size_t)row * 8 + head]     = ps;
                g_al[(size_t)row * 8 + 4 + head] = pd;
            } else if (ALH == 1) {
#pragma unroll
                for (int off = TPR >> 1; off; off >>= 1) {
                    ps += __shfl_xor_sync(0xffffffffu, ps, off);
                    pd += __shfl_xor_sync(0xffffffffu, pd, off);
                }
                if ((tid % TPR) == 0) {
                    g_al1[(size_t)row * 2]     = ps;
                    g_al1[(size_t)row * 2 + 1] = pd;
                }
            }
        }
    }
}
#define SMEM_G128 (2 * (2 * 128 * 80 + 20480))
#define SMEM_G64  (2 * (2 * 64 * 80 + 20480))

__device__ __forceinline__ void unpack8h(uint4 p, float* f) {
    float2 a = __half22float2(*(__half2*)&p.x);
    float2 b = __half22float2(*(__half2*)&p.y);
    float2 c = __half22float2(*(__half2*)&p.z);
    float2 d = __half22float2(*(__half2*)&p.w);
    f[0] = a.x; f[1] = a.y; f[2] = b.x; f[3] = b.y;
    f[4] = c.x; f[5] = c.y; f[6] = d.x; f[7] = d.y;
}
__device__ __forceinline__ void unpack8b(uint4 p, float* f) {
    float2 a = __bfloat1622float2(*(__nv_bfloat162*)&p.x);
    float2 b = __bfloat1622float2(*(__nv_bfloat162*)&p.y);
    float2 c = __bfloat1622float2(*(__nv_bfloat162*)&p.z);
    float2 d = __bfloat1622float2(*(__nv_bfloat162*)&p.w);
    f[0] = a.x; f[1] = a.y; f[2] = b.x; f[3] = b.y;
    f[4] = c.x; f[5] = c.y; f[6] = d.x; f[7] = d.y;
}

// ============  agg0: fp16 features, lane = 8 contiguous channels (one head)  ============
__global__ void k_agg0(const float* __restrict__ b0, const float* __restrict__ g0,
                       const float* __restrict__ be0) {
    int d = (blockIdx.x * blockDim.x + threadIdx.x) >> 5;
    int lane = threadIdx.x & 31;
    if (d >= NN) return;
    int beg = g_rowstart[d], end = g_rowstart[d + 1];
    float ald_l = g_al[d * 8 + 4 + (lane & 3)];
    int hl = lane >> 3;                  // head of channels lane*8 .. lane*8+7
    float acc[8] = {};
    float den = 0.f;
    for (int i = beg; i < end; i += 8) {
        int ii = i + (lane >> 2);
        bool valid = ii < end;
        int s_i = g_esrc[valid ? ii : beg];
        float e = g_al[s_i * 8 + (lane & 3)] + ald_l;
        e = (e > 0.f) ? e : 0.2f * e;
        float w_i = valid ? __expf(e) : 0.f;
#pragma unroll
        for (int k = 0; k < 8; k++) {
            float w = __shfl_sync(0xffffffffu, w_i, k * 4 + hl);
            int   s = __shfl_sync(0xffffffffu, s_i, k * 4);
            uint4 p = *(const uint4*)&g_xwh[(size_t)s * 256 + lane * 8];
            float f[8]; unpack8h(p, f);
#pragma unroll
            for (int j = 0; j < 8; j++) acc[j] += w * f[j];
            den += w;
        }
    }
    float r = 1.f / den;
    int ch = lane * 8;
    float4 bbA = *(const float4*)(b0 + ch), bbB = *(const float4*)(b0 + ch + 4);
    float bb[8] = {bbA.x, bbA.y, bbA.z, bbA.w, bbB.x, bbB.y, bbB.z, bbB.w};
    float t[8]; float s1 = 0.f, s2 = 0.f;
#pragma unroll
    for (int j = 0; j < 8; j++) { t[j] = acc[j] * r + bb[j]; s1 += t[j]; s2 += t[j] * t[j]; }
#pragma unroll
    for (int off = 16; off; off >>= 1) {
        s1 += __shfl_xor_sync(0xffffffffu, s1, off);
        s2 += __shfl_xor_sync(0xffffffffu, s2, off);
    }
    float mu = s1 * (1.f / 256.f);
    float var = s2 * (1.f / 256.f) - mu * mu;
    float rs = rsqrtf(var + 1e-5f);
    float4 ggA = *(const float4*)(g0 + ch),  ggB = *(const float4*)(g0 + ch + 4);
    float4 eeA = *(const float4*)(be0 + ch), eeB = *(const float4*)(be0 + ch + 4);
    float gg[8] = {ggA.x, ggA.y, ggA.z, ggA.w, ggB.x, ggB.y, ggB.z, ggB.w};
    float ee[8] = {eeA.x, eeA.y, eeA.z, eeA.w, eeB.x, eeB.y, eeB.z, eeB.w};
    size_t o = (size_t)d * 256 + ch;
    float fh[8], fl[8];
    unpack8b(*(const uint4*)(g_hhi + o), fh);
    unpack8b(*(const uint4*)(g_hlo + o), fl);
    __nv_bfloat16 qh[8], ql[8];
#pragma unroll
    for (int j = 0; j < 8; j++) {
        float y = fmaxf((t[j] - mu) * rs * gg[j] + ee[j] + (fh[j] + fl[j]), 0.f);
        f2hilo(y, qh[j], ql[j]);
    }
    uint4 oh, ol;
    *(__nv_bfloat162*)&oh.x = __nv_bfloat162(qh[0], qh[1]);
    *(__nv_bfloat162*)&oh.y = __nv_bfloat162(qh[2], qh[3]);
    *(__nv_bfloat162*)&oh.z = __nv_bfloat162(qh[4], qh[5]);
    *(__nv_bfloat162*)&oh.w = __nv_bfloat162(qh[6], qh[7]);
    *(__nv_bfloat162*)&ol.x = __nv_bfloat162(ql[0], ql[1]);
    *(__nv_bfloat162*)&ol.y = __nv_bfloat162(ql[2], ql[3]);
    *(__nv_bfloat162*)&ol.z = __nv_bfloat162(ql[4], ql[5]);
    *(__nv_bfloat162*)&ol.w = __nv_bfloat162(ql[6], ql[7]);
    *(uint4*)(g_h1hi + o) = oh;
    *(uint4*)(g_h1lo + o) = ol;
}

// ============  agg1: fp16 features  ============
__global__ void k_agg1(const float* __restrict__ b1, const float* __restrict__ g1,
                       const float* __restrict__ be1) {
    int d = (blockIdx.x * blockDim.x + threadIdx.x) >> 5;
    int lane = threadIdx.x & 31;
    if (d >= NN) return;
    int beg = g_rowstart[d], end = g_rowstart[d + 1];
    float ald = g_al1[d * 2 + 1];
    float acc[4] = {};
    float den = 0.f;
    for (int i = beg; i < end; i += 8) {
        int ii = i + (lane & 7);
        bool valid = ii < end;
        int s_i = g_esrc[valid ? ii : beg];
        float e = g_al1[s_i * 2] + ald;
        e = (e > 0.f) ? e : 0.2f * e;
        float w_i = valid ? __expf(e) : 0.f;
#pragma unroll
        for (int k = 0; k < 8; k++) {
            float w = __shfl_sync(0xffffffffu, w_i, k);
            int   s = __shfl_sync(0xffffffffu, s_i, k);
            uint2 p = *(const uint2*)&g_xw1h[(size_t)s * 128 + lane * 4];
            float2 a = __half22float2(*(__half2*)&p.x);
            float2 b = __half22float2(*(__half2*)&p.y);
            acc[0] += w * a.x; acc[1] += w * a.y;
            acc[2] += w * b.x; acc[3] += w * b.y;
            den += w;
        }
    }
    float r = 1.f / den;
    int ch = lane * 4;
    float4 bb = *(const float4*)(b1 + ch);
    float t[4] = {acc[0] * r + bb.x, acc[1] * r + bb.y, acc[2] * r + bb.z, acc[3] * r + bb.w};
    float s1 = 0.f, s2 = 0.f;
#pragma unroll
    for (int k = 0; k < 4; k++) { s1 += t[k]; s2 += t[k] * t[k]; }
#pragma unroll
    for (int off = 16; off; off >>= 1) {
        s1 += __shfl_xor_sync(0xffffffffu, s1, off);
        s2 += __shfl_xor_sync(0xffffffffu, s2, off);
    }
    float mu = s1 * (1.f / 128.f);
    float var = s2 * (1.f / 128.f) - mu * mu;
    float rs = rsqrtf(var + 1e-5f);
    float4 gg = *(const float4*)(g1 + ch);
    float4 ee = *(const float4*)(be1 + ch);
    float y[4] = {
        (t[0] - mu) * rs * gg.x + ee.x, (t[1] - mu) * rs * gg.y + ee.y,
        (t[2] - mu) * rs * gg.z + ee.z, (t[3] - mu) * rs * gg.w + ee.w};
    __nv_bfloat16 h[4], l[4];
#pragma unroll
    for (int k = 0; k < 4; k++) f2hilo(y[k], h[k], l[k]);
    size_t o = (size_t)d * 128 + ch;
    *(__nv_bfloat162*)(g_h2hi + o)     = __nv_bfloat162(h[0], h[1]);
    *(__nv_bfloat162*)(g_h2hi + o + 2) = __nv_bfloat162(h[2], h[3]);
    *(__nv_bfloat162*)(g_h2lo + o)     = __nv_bfloat162(l[0], l[1]);
    *(__nv_bfloat162*)(g_h2lo + o + 2) = __nv_bfloat162(l[2], l[3]);
}

// =====================  launch  =====================
extern "C" void kernel_launch(void* const* d_in, const int* in_sizes, int n_in,
                              void* d_out, int out_size) {
    const float* x   = (const float*)d_in[0];
    const void*  ei  = d_in[1];
    const float* Wp  = (const float*)d_in[2];
    const float* bp  = (const float*)d_in[3];
    const float* W0  = (const float*)d_in[4];
    const float* as0 = (const float*)d_in[5];
    const float* ad0 = (const float*)d_in[6];
    const float* b0  = (const float*)d_in[7];
    const float* W1  = (const float*)d_in[8];
    const float* as1 = (const float*)d_in[9];
    const float* ad1 = (const float*)d_in[10];
    const float* b1  = (const float*)d_in[11];
    const float* g0  = (const float*)d_in[12];
    const float* be0 = (const float*)d_in[13];
    const float* g1  = (const float*)d_in[14];
    const float* be1 = (const float*)d_in[15];
    const float* Wo  = (const float*)d_in[16];
    const float* bo  = (const float*)d_in[17];
    float* out = (float*)d_out;

    void *p_xwh, *p_xw1h;
    void *p_xhi, *p_xlo, *p_hhi, *p_hlo, *p_h1hi, *p_h1lo, *p_h2hi, *p_h2lo;
    void *p_WpThi, *p_WpTlo, *p_W0Thi, *p_W0Tlo, *p_W1Thi, *p_W1Tlo, *p_WoThi, *p_WoTlo;
    cudaGetSymbolAddress(&p_xwh,  g_xwh);
    cudaGetSymbolAddress(&p_xw1h, g_xw1h);
    cudaGetSymbolAddress(&p_xhi,  g_xhi);   cudaGetSymbolAddress(&p_xlo,  g_xlo);
    cudaGetSymbolAddress(&p_hhi,  g_hhi);   cudaGetSymbolAddress(&p_hlo,  g_hlo);
    cudaGetSymbolAddress(&p_h1hi, g_h1hi);  cudaGetSymbolAddress(&p_h1lo, g_h1lo);
    cudaGetSymbolAddress(&p_h2hi, g_h2hi);  cudaGetSymbolAddress(&p_h2lo, g_h2lo);
    cudaGetSymbolAddress(&p_WpThi, g_WpThi); cudaGetSymbolAddress(&p_WpTlo, g_WpTlo);
    cudaGetSymbolAddress(&p_W0Thi, g_W0Thi); cudaGetSymbolAddress(&p_W0Tlo, g_W0Tlo);
    cudaGetSymbolAddress(&p_W1Thi, g_W1Thi); cudaGetSymbolAddress(&p_W1Tlo, g_W1Tlo);
    cudaGetSymbolAddress(&p_WoThi, g_WoThi); cudaGetSymbolAddress(&p_WoTlo, g_WoTlo);

    const int nodeBlocks = (NN + 7) / 8;
    const int edgeBlocks = (ETOT + 255) / 256;
    const int gB128 = (NN + 127) / 128;
    const int gB64  = (NN + 63) / 64;

    cudaFuncSetAttribute((const void*)k_gemm_mma<true,  true,  1, false, 0, 128, 1>,
                         cudaFuncAttributeMaxDynamicSharedMemorySize, SMEM_G128);
    cudaFuncSetAttribute((const void*)k_gemm_mma<false, false, 2, false, 4, 128, 2>,
                         cudaFuncAttributeMaxDynamicSharedMemorySize, SMEM_G128);
    cudaFuncSetAttribute((const void*)k_gemm_mma<false, false, 2, false, 1, 64, 0>,
                         cudaFuncAttributeMaxDynamicSharedMemorySize, SMEM_G64);
    cudaFuncSetAttribute((const void*)k_gemm_mma<false, true,  0, true,  0, 64, 0>,
                         cudaFuncAttributeMaxDynamicSharedMemorySize, SMEM_G64);

    // 1: prep (init + detect + cvtA + cvtW)
    k_prep<<<PREP_TOTAL, 256>>>(x, ei, Wp, W0, W1, Wo);

    // 2: count prefix + GEMM1: h = relu(x@Wp + bp) -> bf16 hi/lo
    k_gemm_mma<true, true, 1, false, 0, 128, 1>
        <<<edgeBlocks + gB128 * 2, 256, SMEM_G128>>>(
        (const __nv_bfloat16*)p_xhi, (const __nv_bfloat16*)p_xlo,
        (const __nv_bfloat16*)p_WpThi, (const __nv_bfloat16*)p_WpTlo,
        bp, nullptr, (__nv_bfloat16*)p_hhi, (__nv_bfloat16*)p_hlo,
        nullptr, nullptr, ei, edgeBlocks, NN, 256, 256);

    // 3-4: scan
    k_scan1<<<SCANB, 256>>>();
    k_scan2<<<SCANB, 256>>>();

    // 5: scatter prefix + GEMM2: xw (fp16) = h@W0, logits al0 fused (fp32 accums)
    k_gemm_mma<false, false, 2, false, 4, 128, 2>
        <<<edgeBlocks + gB128 * 2, 256, SMEM_G128>>>(
        (const __nv_bfloat16*)p_hhi, (const __nv_bfloat16*)p_hlo,
        (const __nv_bfloat16*)p_W0Thi, (const __nv_bfloat16*)p_W0Tlo,
        nullptr, nullptr, (__nv_bfloat16*)p_xwh, nullptr, as0, ad0, ei, edgeBlocks, NN, 256, 256);

    // 6: agg0 + LN0 + residual + relu -> h1 hi/lo
    k_agg0<<<nodeBlocks, 256>>>(b0, g0, be0);

    // 7: GEMM3 (TM=64): xw1 (fp16) = h1@W1, logits al1 fused
    k_gemm_mma<false, false, 2, false, 1, 64, 0><<<gB64, 256, SMEM_G64>>>(
        (const __nv_bfloat16*)p_h1hi, (const __nv_bfloat16*)p_h1lo,
        (const __nv_bfloat16*)p_W1Thi, (const __nv_bfloat16*)p_W1Tlo,
        nullptr, nullptr, (__nv_bfloat16*)p_xw1h, nullptr, as1, ad1, nullptr, 0, NN, 256, 128);

    // 8: agg1 + LN1 -> h2 hi/lo
    k_agg1<<<nodeBlocks, 256>>>(b1, g1, be1);

    // 9: GEMM4 (TM=64): out = rownorm(h2@Wo + bo)
    k_gemm_mma<false, true, 0, true, 0, 64, 0><<<gB64, 256, SMEM_G64>>>(
        (const __nv_bfloat16*)p_h2hi, (const __nv_bfloat16*)p_h2lo,
        (const __nv_bfloat16*)p_WoThi, (const __nv_bfloat16*)p_WoTlo,
        bo, out, nullptr, nullptr, nullptr, nullptr, nullptr, 0, NN, 128, 128);
}